// round 10
// baseline (speedup 1.0000x reference)
#include <cuda_runtime.h>

// Problem shape (fixed by the dataset)
#define BATCH 8
#define CH    256
#define HH    128
#define WW    128
#define HO    64
#define WO    64
#define NPLANES 2048

// Dynamic smem layout (floats). Log tables row-padded: input row r stored at
// table row r+1; table row 0 (= input row -1) is -inf so top-edge windows
// contribute ex2(-inf)=0 with no predication.
//   le[129][64] : log2(relu(even cols)), le[r+1][k] = col 2k
//   lo[129][68] : log2(relu(odd cols)),  lo[r+1][j] = col 2j-1 (j=0 = left pad)
//                 stride 68 => rows 16B-aligned (68*4 = 272 = 16*17)
//   sc[48]      : [0..31] warp max partials, [32] invm, [33..41] w1 raw
#define LE_OFF 0
#define LO_OFF (129 * 64)
#define SC_OFF (LO_OFF + 129 * 68)
#define SMEM_FLOATS (SC_OFF + 48)
#define SMEM_BYTES  (SMEM_FLOATS * 4)

#define NINF __int_as_float(0xff800000)

__device__ __forceinline__ float f_lg2(float x) {
    float y; asm("lg2.approx.f32 %0, %1;" : "=f"(y) : "f"(x)); return y;
}
__device__ __forceinline__ float f_ex2(float x) {
    float y; asm("ex2.approx.f32 %0, %1;" : "=f"(y) : "f"(x)); return y;
}
__device__ __forceinline__ float f_rcp(float x) {
    float y; asm("rcp.approx.f32 %0, %1;" : "=f"(y) : "f"(x)); return y;
}

// One block = one (b,c) plane. 1024 threads = (16, 64).
// Phase 1: stream plane once, build padded log tables + plane max.
// Phase 2: thread (tx,ty) -> outputs ho=ty, wo=4tx..4tx+3 (wide loads/stores).
__global__ __launch_bounds__(1024, 2) void fused_ppool_kernel(
    const float* __restrict__ bottom,
    const float* __restrict__ w1,
    const float* __restrict__ a1,
    const float* __restrict__ w2,
    const float* __restrict__ b2,
    float* __restrict__ out_res,
    float* __restrict__ out_p)
{
    extern __shared__ float smem[];
    float* le = smem + LE_OFF;
    float* lo = smem + LO_OFF;
    float* sc = smem + SC_OFF;

    const int plane = blockIdx.x;
    const int c = plane & (CH - 1);
    const float* __restrict__ src = bottom + (size_t)plane * (HH * WW);

    const int tx = threadIdx.x;          // 0..15
    const int ty = threadIdx.y;          // 0..63
    const int t  = ty * 16 + tx;         // 0..1023
    const int wid = t >> 5, lid = t & 31;

    if (t < 9) sc[33 + t] = __ldg(&w1[c * 9 + t]);
    // -inf pads: le row 0; lo col j=0 (all rows); lo row 0 (j=1..64)
    if (t < 64)               le[t]           = NINF;
    if (t < 129)              lo[t * 68]      = NINF;
    if (t >= 129 && t < 193)  lo[t - 128]     = NINF;

    // ---- Phase 1: stream plane (8192 float2), log tables + |x| max ----
    const float2* s2 = (const float2*)src;
    float mx = 0.f;
    #pragma unroll
    for (int i = 0; i < 8; i++) {
        int idx = t + i * 1024;          // float2 idx: row = idx>>6, k = idx&63
        int r = idx >> 6, k = idx & 63;
        float2 v = __ldg(s2 + idx);
        le[(r + 1) * 64 + k]     = f_lg2(fmaxf(v.x, 0.f));   // lg2(0) = -inf
        lo[(r + 1) * 68 + k + 1] = f_lg2(fmaxf(v.y, 0.f));
        mx = fmaxf(mx, fmaxf(fabsf(v.x), fabsf(v.y)));
    }
    #pragma unroll
    for (int o = 16; o; o >>= 1) mx = fmaxf(mx, __shfl_xor_sync(0xffffffffu, mx, o));
    if (lid == 0) sc[wid] = mx;
    __syncthreads();
    if (t < 32) {
        float m = sc[t];
        #pragma unroll
        for (int o = 16; o; o >>= 1) m = fmaxf(m, __shfl_xor_sync(0xffffffffu, m, o));
        if (t == 0) sc[32] = 1.0f / (m + 1.0f);
    }
    __syncthreads();

    const float invm = sc[32];
    const float av = __ldg(&a1[c]);
    const float wv = __ldg(&w2[c]);
    const float bv = __ldg(&b2[c]);

    // ---- Phase 2: 4 horizontally-adjacent outputs per thread ----
    const int ho = ty;
    const int rbase = 2 * ho - 1;            // top tap input row (-1 for ho=0)

    // Conv: windows span cols 8tx-1 .. 8tx+7 over 3 rows.
    float c0 = 0.f, c1 = 0.f, c2 = 0.f, c3 = 0.f;
    {
        const float* srow = src + rbase * WW + 8 * tx;
        #pragma unroll
        for (int ki = 0; ki < 3; ki++) {
            const bool rv = (rbase + ki) >= 0;   // only ho=0,ki=0 is out
            float  vm = (rv && tx > 0) ? __ldg(srow - 1) : 0.f;
            float4 q0 = rv ? __ldg((const float4*)srow)
                           : make_float4(0.f, 0.f, 0.f, 0.f);
            float4 q1 = rv ? __ldg((const float4*)(srow + 4))
                           : make_float4(0.f, 0.f, 0.f, 0.f);
            const float wa = sc[33 + ki * 3];
            const float wb = sc[34 + ki * 3];
            const float wc = sc[35 + ki * 3];
            c0 = fmaf(wa, vm,   fmaf(wb, q0.x, fmaf(wc, q0.y, c0)));
            c1 = fmaf(wa, q0.y, fmaf(wb, q0.z, fmaf(wc, q0.w, c1)));
            c2 = fmaf(wa, q0.w, fmaf(wb, q1.x, fmaf(wc, q1.y, c2)));
            c3 = fmaf(wa, q1.y, fmaf(wb, q1.z, fmaf(wc, q1.w, c3)));
            srow += WW;
        }
    }

    // PReLU + affine + clamp -> exponents p0..p3
    float p0, p1, p2, p3;
    {
        float x;
        c0 *= invm; x = c0 > 0.f ? c0 : av * c0;
        p0 = fminf(fmaxf(fmaf(x, wv, bv), 1.0f), 110.0f);
        c1 *= invm; x = c1 > 0.f ? c1 : av * c1;
        p1 = fminf(fmaxf(fmaf(x, wv, bv), 1.0f), 110.0f);
        c2 *= invm; x = c2 > 0.f ? c2 : av * c2;
        p2 = fminf(fmaxf(fmaf(x, wv, bv), 1.0f), 110.0f);
        c3 *= invm; x = c3 > 0.f ? c3 : av * c3;
        p3 = fminf(fmaxf(fmaf(x, wv, bv), 1.0f), 110.0f);
    }

    // Pooling: per table row tr = 2ho+ki, even logs k=4tx..4tx+3 (LDS.128),
    // odd logs j=4tx..4tx+4 (LDS.128 + LDS.32).
    float s0 = 0.f, s1 = 0.f, s2v = 0.f, s3 = 0.f;
    {
        const float* lr = le + (2 * ho) * 64 + 4 * tx;
        const float* orow = lo + (2 * ho) * 68 + 4 * tx;
        #pragma unroll
        for (int ki = 0; ki < 3; ki++) {
            float4 eq = *(const float4*)lr;      // even cols 2wo (u=0..3)
            float4 oq = *(const float4*)orow;    // odd cols 2wo-1 (u=0..3)
            float  o4 = orow[4];                 // odd col 2wo+7 (right tap u=3)
            s0  += f_ex2(p0 * oq.x) + f_ex2(p0 * eq.x) + f_ex2(p0 * oq.y);
            s1  += f_ex2(p1 * oq.y) + f_ex2(p1 * eq.y) + f_ex2(p1 * oq.z);
            s2v += f_ex2(p2 * oq.z) + f_ex2(p2 * eq.z) + f_ex2(p2 * oq.w);
            s3  += f_ex2(p3 * oq.w) + f_ex2(p3 * eq.w) + f_ex2(p3 * o4);
            lr += 64; orow += 68;
        }
    }

    // Final root + vectorized stores
    float4 rres, rp;
    {
        float mean;
        mean = fmaf(s0,  (1.0f / 9.0f), 1e-12f);
        rres.x = f_ex2(f_lg2(mean) * f_rcp(p0));
        mean = fmaf(s1,  (1.0f / 9.0f), 1e-12f);
        rres.y = f_ex2(f_lg2(mean) * f_rcp(p1));
        mean = fmaf(s2v, (1.0f / 9.0f), 1e-12f);
        rres.z = f_ex2(f_lg2(mean) * f_rcp(p2));
        mean = fmaf(s3,  (1.0f / 9.0f), 1e-12f);
        rres.w = f_ex2(f_lg2(mean) * f_rcp(p3));
        rp = make_float4(p0, p1, p2, p3);
    }

    const size_t o = ((size_t)plane * HO + ho) * WO + 4 * tx;
    *(float4*)(out_res + o) = rres;
    *(float4*)(out_p   + o) = rp;
}

extern "C" void kernel_launch(void* const* d_in, const int* in_sizes, int n_in,
                              void* d_out, int out_size) {
    const float* bottom = (const float*)d_in[0];
    const float* w1     = (const float*)d_in[1];
    const float* a1     = (const float*)d_in[2];
    const float* w2     = (const float*)d_in[3];
    const float* b2     = (const float*)d_in[4];
    float* out = (float*)d_out;
    const size_t N = (size_t)BATCH * CH * HO * WO;   // elements per output tensor

    cudaFuncSetAttribute(fused_ppool_kernel,
                         cudaFuncAttributeMaxDynamicSharedMemorySize, SMEM_BYTES);

    dim3 blk(16, 64);
    fused_ppool_kernel<<<NPLANES, blk, SMEM_BYTES>>>(bottom, w1, a1, w2, b2,
                                                     out, out + N);

    (void)in_sizes; (void)n_in; (void)out_size;
}

// round 11
// speedup vs baseline: 1.0938x; 1.0938x over previous
#include <cuda_runtime.h>

// Problem shape (fixed by the dataset)
#define BATCH 8
#define CH    256
#define HH    128
#define WW    128
#define HO    64
#define WO    64
#define NPLANES 2048

// Dynamic smem layout (floats). Log tables row-padded: input row r stored at
// table row r+1; table row 0 (= input row -1) is -inf so top-edge windows
// contribute ex2(-inf)=0 with no predication.
//   le[129][64] : log2(relu(even cols)), le[r+1][k] = col 2k
//   lo[129][65] : log2(relu(odd cols)),  lo[r+1][j] = col 2j-1 (j=0 = left pad)
//   sc[48]      : [0..15] warp max partials, [32] invm, [33..41] w1 raw
#define LE_OFF 0
#define LO_OFF (129 * 64)
#define SC_OFF (LO_OFF + 129 * 65)
#define SMEM_FLOATS (SC_OFF + 48)
#define SMEM_BYTES  (SMEM_FLOATS * 4)

#define NINF __int_as_float(0xff800000)

__device__ __forceinline__ float f_lg2(float x) {
    float y; asm("lg2.approx.f32 %0, %1;" : "=f"(y) : "f"(x)); return y;
}
__device__ __forceinline__ float f_ex2(float x) {
    float y; asm("ex2.approx.f32 %0, %1;" : "=f"(y) : "f"(x)); return y;
}
__device__ __forceinline__ float f_rcp(float x) {
    float y; asm("rcp.approx.f32 %0, %1;" : "=f"(y) : "f"(x)); return y;
}

// One block = one (b,c) plane. 512 threads = (64, 8), 64 regs/thread.
// Phase 1: stream plane once, build padded log tables + plane max.
// Phase 2: thread (tx,ty) -> outputs wo=tx, ho=8ty..8ty+7 with carried-row
// reuse (shared window row kept in registers between consecutive outputs).
__global__ __launch_bounds__(512, 2) void fused_ppool_kernel(
    const float* __restrict__ bottom,
    const float* __restrict__ w1,
    const float* __restrict__ a1,
    const float* __restrict__ w2,
    const float* __restrict__ b2,
    float* __restrict__ out_res,
    float* __restrict__ out_p)
{
    extern __shared__ float smem[];
    float* le = smem + LE_OFF;
    float* lo = smem + LO_OFF;
    float* sc = smem + SC_OFF;

    const int plane = blockIdx.x;
    const int c = plane & (CH - 1);
    const float* __restrict__ src = bottom + (size_t)plane * (HH * WW);

    const int tx = threadIdx.x;          // 0..63 -> wo
    const int ty = threadIdx.y;          // 0..7
    const int t  = ty * 64 + tx;         // 0..511
    const int wid = t >> 5, lid = t & 31;

    if (t < 9) sc[33 + t] = __ldg(&w1[c * 9 + t]);
    // -inf pads: le row 0; lo col j=0 (all 129 rows); lo row 0 (j=1..64)
    if (t < 64)               le[t]       = NINF;
    if (t < 129)              lo[t * 65]  = NINF;
    if (t >= 129 && t < 193)  lo[t - 128] = NINF;

    // ---- Phase 1: stream plane (8192 float2), log tables + |x| max ----
    const float2* s2 = (const float2*)src;
    float mx = 0.f;
    #pragma unroll
    for (int i = 0; i < 16; i++) {
        int idx = t + i * 512;           // float2 idx: row = idx>>6, k = idx&63
        int r = idx >> 6, k = idx & 63;
        float2 v = __ldg(s2 + idx);
        le[(r + 1) * 64 + k]     = f_lg2(fmaxf(v.x, 0.f));   // lg2(0) = -inf
        lo[(r + 1) * 65 + k + 1] = f_lg2(fmaxf(v.y, 0.f));
        mx = fmaxf(mx, fmaxf(fabsf(v.x), fabsf(v.y)));
    }
    #pragma unroll
    for (int o = 16; o; o >>= 1) mx = fmaxf(mx, __shfl_xor_sync(0xffffffffu, mx, o));
    if (lid == 0) sc[wid] = mx;
    __syncthreads();
    if (t < 16) {
        float m = sc[t];
        #pragma unroll
        for (int o = 8; o; o >>= 1) m = fmaxf(m, __shfl_xor_sync(0xffffu, m, o));
        if (t == 0) sc[32] = 1.0f / (m + 1.0f);
    }
    __syncthreads();

    const float invm = sc[32];
    float w[9];
    #pragma unroll
    for (int i = 0; i < 9; i++) w[i] = sc[33 + i];
    const float av = __ldg(&a1[c]);
    const float wv = __ldg(&w2[c]);
    const float bv = __ldg(&b2[c]);

    // ---- Phase 2: 8 vertically-adjacent outputs, carried-row reuse ----
    const int ho0 = ty * 8;

    // Carried top row = input row 2*ho0-1 (table row 2*ho0).
    // Raw taps (predicated: row -1 only when ty==0); logs from padded table.
    float am, ax, ay, la0, la1, la2;
    {
        const float* srowt = src + (2 * ho0 - 1) * WW + 2 * tx;
        bool rv = (ho0 > 0);
        am = (rv && tx > 0) ? __ldg(srowt - 1) : 0.f;
        float2 q = rv ? __ldg((const float2*)srowt) : make_float2(0.f, 0.f);
        ax = q.x; ay = q.y;
        la0 = lo[2 * ho0 * 65 + tx];
        la1 = le[2 * ho0 * 64 + tx];
        la2 = lo[2 * ho0 * 65 + tx + 1];
    }

    const float* srow = src + (2 * ho0) * WW + 2 * tx;   // mid row of 1st win
    const float* pe = le + (2 * ho0 + 1) * 64 + tx;
    const float* po = lo + (2 * ho0 + 1) * 65 + tx;
    size_t o = ((size_t)plane * HO + ho0) * WO + tx;

    #pragma unroll
    for (int g = 0; g < 8; g++) {
        // Load mid (2ho) and bottom (2ho+1) rows — always valid rows 0..127.
        float  bm = (tx > 0) ? __ldg(srow - 1) : 0.f;
        float2 bq = __ldg((const float2*)srow);
        float  cm = (tx > 0) ? __ldg(srow + WW - 1) : 0.f;
        float2 cq = __ldg((const float2*)(srow + WW));
        float lb0 = po[0],  lb1 = pe[0],  lb2 = po[1];
        float lc0 = po[65], lc1 = pe[64], lc2 = po[66];

        // Depthwise conv; scale by invm afterwards (linearity).
        float conv =              w[0] * am;
        conv = fmaf(w[1], ax,   conv);
        conv = fmaf(w[2], ay,   conv);
        conv = fmaf(w[3], bm,   conv);
        conv = fmaf(w[4], bq.x, conv);
        conv = fmaf(w[5], bq.y, conv);
        conv = fmaf(w[6], cm,   conv);
        conv = fmaf(w[7], cq.x, conv);
        conv = fmaf(w[8], cq.y, conv);
        conv *= invm;

        // PReLU + affine + clamp -> exponent p
        float x = conv > 0.f ? conv : av * conv;
        float p = fminf(fmaxf(fmaf(x, wv, bv), 1.0f), 110.0f);

        // Power-mean over the 3x3 window
        float sum = f_ex2(p * la0) + f_ex2(p * la1) + f_ex2(p * la2)
                  + f_ex2(p * lb0) + f_ex2(p * lb1) + f_ex2(p * lb2)
                  + f_ex2(p * lc0) + f_ex2(p * lc1) + f_ex2(p * lc2);

        float mean = fmaf(sum, (1.0f / 9.0f), 1e-12f);
        float res  = f_ex2(f_lg2(mean) * f_rcp(p));

        out_res[o] = res;
        out_p[o]   = p;

        // Shift: bottom row becomes next window's top row.
        am = cm; ax = cq.x; ay = cq.y;
        la0 = lc0; la1 = lc1; la2 = lc2;
        srow += 2 * WW;
        pe += 2 * 64; po += 2 * 65;
        o += WO;
    }
}

extern "C" void kernel_launch(void* const* d_in, const int* in_sizes, int n_in,
                              void* d_out, int out_size) {
    const float* bottom = (const float*)d_in[0];
    const float* w1     = (const float*)d_in[1];
    const float* a1     = (const float*)d_in[2];
    const float* w2     = (const float*)d_in[3];
    const float* b2     = (const float*)d_in[4];
    float* out = (float*)d_out;
    const size_t N = (size_t)BATCH * CH * HO * WO;   // elements per output tensor

    cudaFuncSetAttribute(fused_ppool_kernel,
                         cudaFuncAttributeMaxDynamicSharedMemorySize, SMEM_BYTES);

    dim3 blk(64, 8);
    fused_ppool_kernel<<<NPLANES, blk, SMEM_BYTES>>>(bottom, w1, a1, w2, b2,
                                                     out, out + N);

    (void)in_sizes; (void)n_in; (void)out_size;
}

// round 13
// speedup vs baseline: 1.2062x; 1.1029x over previous
#include <cuda_runtime.h>

// Problem shape (fixed by the dataset)
#define BATCH 8
#define CH    256
#define HH    128
#define WW    128
#define HO    64
#define WO    64
#define NPLANES 2048

// Dynamic smem layout. Paired log table, row-padded:
//   lp[129][66] of float2:  lp[r+1][j] = { log2(relu(col 2j-1)),
//                                          log2(relu(col 2j)) }   (input row r)
//   table row 0 (= input row -1) and col j=0 .x (= col -1) are -inf pads, so
//   out-of-range taps contribute ex2(-inf) = 0 with no predication.
//   sc[48] : [0..15] warp max partials, [32] invm, [33..41] w1 raw
#define LP_OFF 0
#define SC_OFF (129 * 66 * 2)
#define SMEM_FLOATS (SC_OFF + 48)
#define SMEM_BYTES  (SMEM_FLOATS * 4)

#define NINF __int_as_float(0xff800000)

__device__ __forceinline__ float f_lg2(float x) {
    float y; asm("lg2.approx.f32 %0, %1;" : "=f"(y) : "f"(x)); return y;
}
__device__ __forceinline__ float f_ex2(float x) {
    float y; asm("ex2.approx.f32 %0, %1;" : "=f"(y) : "f"(x)); return y;
}
__device__ __forceinline__ float f_rcp(float x) {
    float y; asm("rcp.approx.f32 %0, %1;" : "=f"(y) : "f"(x)); return y;
}

// One block = one (b,c) plane. 512 threads = (64, 8), 3 blocks/SM (42 regs).
// Phase 1: stream plane once, build padded paired-log table + plane max.
// Phase 2: thread (tx,ty) -> outputs wo=tx, ho=8ty..8ty+7 with carried-row
// reuse (shared window row kept in registers between consecutive outputs).
__global__ __launch_bounds__(512, 3) void fused_ppool_kernel(
    const float* __restrict__ bottom,
    const float* __restrict__ w1,
    const float* __restrict__ a1,
    const float* __restrict__ w2,
    const float* __restrict__ b2,
    float* __restrict__ out_res,
    float* __restrict__ out_p)
{
    extern __shared__ float smem[];
    float2* lp = (float2*)(smem + LP_OFF);
    float*  sc = smem + SC_OFF;

    const int plane = blockIdx.x;
    const int c = plane & (CH - 1);
    const float* __restrict__ src = bottom + (size_t)plane * (HH * WW);

    const int tx = threadIdx.x;          // 0..63 -> wo
    const int ty = threadIdx.y;          // 0..7
    const int t  = ty * 64 + tx;         // 0..511
    const int wid = t >> 5, lid = t & 31;

    if (t < 9) sc[33 + t] = __ldg(&w1[c * 9 + t]);
    // -inf pads: table row 0 full pairs (j=0..64); col -1 (.x) for rows 1..128
    if (t < 65)              lp[t] = make_float2(NINF, NINF);
    if (t >= 65 && t < 193)  lp[(t - 64) * 66].x = NINF;

    // ---- Phase 1: stream plane (8192 float2), paired-log table + |x| max ----
    const float2* s2 = (const float2*)src;
    float mx = 0.f;
    #pragma unroll
    for (int i = 0; i < 16; i++) {
        int idx = t + i * 512;           // float2 idx: row = idx>>6, k = idx&63
        int r = idx >> 6, k = idx & 63;
        float2 v = __ldg(s2 + idx);
        lp[(r + 1) * 66 + k].y     = f_lg2(fmaxf(v.x, 0.f));  // col 2k
        lp[(r + 1) * 66 + k + 1].x = f_lg2(fmaxf(v.y, 0.f));  // col 2k+1
        mx = fmaxf(mx, fmaxf(fabsf(v.x), fabsf(v.y)));
    }
    #pragma unroll
    for (int o = 16; o; o >>= 1) mx = fmaxf(mx, __shfl_xor_sync(0xffffffffu, mx, o));
    if (lid == 0) sc[wid] = mx;
    __syncthreads();
    if (t < 16) {
        float m = sc[t];
        #pragma unroll
        for (int o = 8; o; o >>= 1) m = fmaxf(m, __shfl_xor_sync(0xffffu, m, o));
        if (t == 0) sc[32] = 1.0f / (m + 1.0f);
    }
    __syncthreads();

    // Fold 1/m into the conv weights (conv(x/m) = conv_{w/m}(x)).
    const float invm = sc[32];
    float w[9];
    #pragma unroll
    for (int i = 0; i < 9; i++) w[i] = sc[33 + i] * invm;
    const float av = __ldg(&a1[c]);
    const float wv = __ldg(&w2[c]);
    const float bv = __ldg(&b2[c]);

    // ---- Phase 2: 8 vertically-adjacent outputs, carried-row reuse ----
    const int ho0 = ty * 8;

    // Carried top row = input row 2*ho0-1 (table row 2*ho0).
    float am, ax, ay, la0, la1, la2;
    {
        const float* srowt = src + (2 * ho0 - 1) * WW + 2 * tx;
        bool rv = (ho0 > 0);
        am = (rv && tx > 0) ? __ldg(srowt - 1) : 0.f;
        float2 q = rv ? __ldg((const float2*)srowt) : make_float2(0.f, 0.f);
        ax = q.x; ay = q.y;
        float2 lq = lp[2 * ho0 * 66 + tx];
        la0 = lq.x; la1 = lq.y;
        la2 = lp[2 * ho0 * 66 + tx + 1].x;
    }

    const float*  srow = src + (2 * ho0) * WW + 2 * tx;   // mid row of 1st win
    const float2* lrow = lp + (2 * ho0 + 1) * 66 + tx;
    size_t o = ((size_t)plane * HO + ho0) * WO + tx;

    #pragma unroll
    for (int g = 0; g < 8; g++) {
        // Load mid (2ho) and bottom (2ho+1) rows — always valid rows 0..127.
        float  bm = (tx > 0) ? __ldg(srow - 1) : 0.f;
        float2 bq = __ldg((const float2*)srow);
        float  cm = (tx > 0) ? __ldg(srow + WW - 1) : 0.f;
        float2 cq = __ldg((const float2*)(srow + WW));
        float2 lbq = lrow[0];
        float  lb2 = lrow[1].x;
        float2 lcq = lrow[66];
        float  lc2 = lrow[67].x;

        // Depthwise conv (weights pre-scaled by 1/m).
        float conv =              w[0] * am;
        conv = fmaf(w[1], ax,   conv);
        conv = fmaf(w[2], ay,   conv);
        conv = fmaf(w[3], bm,   conv);
        conv = fmaf(w[4], bq.x, conv);
        conv = fmaf(w[5], bq.y, conv);
        conv = fmaf(w[6], cm,   conv);
        conv = fmaf(w[7], cq.x, conv);
        conv = fmaf(w[8], cq.y, conv);

        // PReLU + affine + clamp -> exponent p
        float x = conv > 0.f ? conv : av * conv;
        float p = fminf(fmaxf(fmaf(x, wv, bv), 1.0f), 110.0f);

        // Power-mean over the 3x3 window
        float sum = f_ex2(p * la0)   + f_ex2(p * la1)   + f_ex2(p * la2)
                  + f_ex2(p * lbq.x) + f_ex2(p * lbq.y) + f_ex2(p * lb2)
                  + f_ex2(p * lcq.x) + f_ex2(p * lcq.y) + f_ex2(p * lc2);

        float mean = fmaf(sum, (1.0f / 9.0f), 1e-12f);
        float res  = f_ex2(f_lg2(mean) * f_rcp(p));

        out_res[o] = res;
        out_p[o]   = p;

        // Shift: bottom row becomes next window's top row.
        am = cm; ax = cq.x; ay = cq.y;
        la0 = lcq.x; la1 = lcq.y; la2 = lc2;
        srow += 2 * WW;
        lrow += 2 * 66;
        o += WO;
    }
}

extern "C" void kernel_launch(void* const* d_in, const int* in_sizes, int n_in,
                              void* d_out, int out_size) {
    const float* bottom = (const float*)d_in[0];
    const float* w1     = (const float*)d_in[1];
    const float* a1     = (const float*)d_in[2];
    const float* w2     = (const float*)d_in[3];
    const float* b2     = (const float*)d_in[4];
    float* out = (float*)d_out;
    const size_t N = (size_t)BATCH * CH * HO * WO;   // elements per output tensor

    cudaFuncSetAttribute(fused_ppool_kernel,
                         cudaFuncAttributeMaxDynamicSharedMemorySize, SMEM_BYTES);

    dim3 blk(64, 8);
    fused_ppool_kernel<<<NPLANES, blk, SMEM_BYTES>>>(bottom, w1, a1, w2, b2,
                                                     out, out + N);

    (void)in_sizes; (void)n_in; (void)out_size;
}